// round 16
// baseline (speedup 1.0000x reference)
#include <cuda_runtime.h>

// InterConv: B=2048, F=39, E=64, C=64, P=741
// out[b, c*P + p] = relu( U[c][ii[p]] + V[c][jj[p]] ),  U = x@Wi^T + bias, V = x@Wj^T
//
// 512 threads/CTA, 3 CTAs/SM (48 warps), <=42 regs (20 accum regs via k-split).
// smem (floats), 48.7 KB:
//   phase 0/1: xs [0,2720) rows stride 17 f4;  Wi [2720,7072)  Wj [7072,11424)
//              (stride 17 f4);  tab [11424,12168) built in phase 0
//   phase 2 overlay: Uc [0,2624)  Vc [2624,5248)
//
// Phase 1 (octet map, R8-proven): cs = (w>>1)*8 + (lane&7), fb = (w&1)*4 + (lane>>3);
//   thread computes U/V[cs][f], f = fb + 8k (k<5). Per e4/warp: 2 W-LDS.128
//   (8 rows x 4-bcast, stride-17 -> 1 wf) + 5 xs-LDS.128 (4 rows x 8-bcast, 1 wf).
//
// Phase 2: R11 fused row-pairs (p0(r)==p0(r+32)), 22-entry register tab window;
//   16 warps x 2 pairs.

#define FN 39
#define EN 64
#define CN 64
#define PN 741            // 39*38/2
#define OUTB (CN * PN)    // 47424 floats per batch
#define THREADS 512

#define XS_OFF  0                       // 40 rows x 17 f4 = 2720 floats
#define WI_OFF  2720                    // 64 rows x 17 f4 = 4352 floats
#define WJ_OFF  7072
#define TAB_OFF 11424                   // 744 floats
#define UC_OFF  0                       // overlay (xs/W dead)
#define VC_OFF  2624
#define SMEM_FLOATS 12168
#define SMEM_BYTES  (SMEM_FLOATS * 4)   // 48672

// packed fp32x2 FMA (Blackwell; exact fp32 semantics, 2x FFMA throughput)
#define FMA_F32X2(acc, a, b) \
    asm("fma.rn.f32x2 %0, %1, %2, %0;" : "+l"(acc) : "l"(a), "l"(b))

extern __shared__ float smem[];

__global__ void __launch_bounds__(THREADS, 3)
interconv_kernel(const float* __restrict__ x,
                 const float* __restrict__ W,
                 const float* __restrict__ bias,
                 float* __restrict__ out)
{
    const int tid = threadIdx.x;
    const long long b = blockIdx.x;
    unsigned* tab = (unsigned*)(smem + TAB_OFF);

    // ---- Phase 0: stage x (stride 17) and W (stride 17); build tab -------
    {
        float4* xs4 = (float4*)(smem + XS_OFF);
        const float4* xb4 = (const float4*)(x + b * (long long)(FN * EN));
        #pragma unroll
        for (int it = 0; it < 2; it++) {
            int idx = tid + it * THREADS;
            if (idx < (FN * EN) / 4)
                xs4[idx + (idx >> 4)] = xb4[idx];   // slot f*17 + e4
        }
        if (tid < EN) {                             // zero pad row f=39
            int e4 = tid >> 2, r = tid & 3;
            smem[XS_OFF + (39 * 17 + e4) * 4 + r] = 0.f;
        }

        // W gmem: [c][128] floats (k=0 -> Wi, k=1 -> Wj); smem stride 17 f4
        float4* Wi4 = (float4*)(smem + WI_OFF);
        float4* Wj4 = (float4*)(smem + WJ_OFF);
        const float4* Wg4 = (const float4*)W;
        #pragma unroll
        for (int it = 0; it < 4; it++) {
            int idx = tid + it * THREADS;           // 2048 float4 total
            int c = idx >> 5, q = idx & 31;
            float4 w = Wg4[idx];
            if (q < 16) Wi4[c * 17 + q] = w;
            else        Wj4[c * 17 + (q - 16)] = w;
        }

        // pair table (np.triu_indices(F,1) row-major): byte offsets i*4 | j*4<<16
        for (int p = tid; p < PN; p += THREADS) {
            int i = 0, rem = p;
            while (rem >= FN - 1 - i) { rem -= FN - 1 - i; i++; }
            int j = i + 1 + rem;
            tab[p] = (unsigned)(i * 4) | ((unsigned)(j * 4) << 16);
        }
    }
    __syncthreads();

    // ---- Phase 1: U = x @ Wi^T + b, V = x @ Wj^T  (f32x2, octet map) -----
    const int lane = tid & 31;
    const int wrp  = tid >> 5;                      // 0..15
    const int cs = (wrp >> 1) * 8 + (lane & 7);     // c-row 0..63
    const int fb = (wrp & 1) * 4 + (lane >> 3);     // f = fb + 8k, k<5

    unsigned long long au[5], av[5];
    #pragma unroll
    for (int k = 0; k < 5; k++) { au[k] = 0ull; av[k] = 0ull; }

    {
        const ulonglong2* xs2 = (const ulonglong2*)(smem + XS_OFF);   // [f*17+e4]
        const ulonglong2* Wi2 = (const ulonglong2*)(smem + WI_OFF);   // [c*17+e4]
        const ulonglong2* Wj2 = (const ulonglong2*)(smem + WJ_OFF);

        #pragma unroll
        for (int e4 = 0; e4 < 16; e4++) {
            ulonglong2 wi = Wi2[cs * 17 + e4];
            ulonglong2 wj = Wj2[cs * 17 + e4];
            #pragma unroll
            for (int k = 0; k < 5; k++) {
                ulonglong2 xv = xs2[(fb + 8 * k) * 17 + e4];  // f=39 row is zeros
                FMA_F32X2(au[k], xv.x, wi.x);
                FMA_F32X2(au[k], xv.y, wi.y);
                FMA_F32X2(av[k], xv.x, wj.x);
                FMA_F32X2(av[k], xv.y, wj.y);
            }
        }
    }
    __syncthreads();   // all xs/W reads done; safe to overlay

    // ---- Phase 1b: write Uc/Vc (transposed, stride 41) ------------------
    float* Uc = smem + UC_OFF;                 // [c][41]
    float* Vc = smem + VC_OFF;                 // [c][41]
    {
        const float bc = __ldg(bias + cs);
        #pragma unroll
        for (int k = 0; k < 5; k++) {
            int f = fb + 8 * k;                // f<=39; f=39 row never read
            float ulo = __uint_as_float((unsigned)au[k]);
            float uhi = __uint_as_float((unsigned)(au[k] >> 32));
            float vlo = __uint_as_float((unsigned)av[k]);
            float vhi = __uint_as_float((unsigned)(av[k] >> 32));
            Uc[cs * 41 + f] = ulo + uhi + bc;  // bias folded into U
            Vc[cs * 41 + f] = vlo + vhi;
        }
    }
    __syncthreads();

    // ---- Phase 2: expansion + relu, fused row pairs, register tab --------
    float* outb = out + b * (long long)OUTB;

    #pragma unroll 1
    for (int kk = 0; kk < 2; kk++) {
        const int r  = wrp * 2 + kk;          // rows r and r+32 share p0
        const int p0 = (27 * r) & 31;

        // preload the 22-entry aligned tab window into registers
        unsigned tw[22];
        {
            const unsigned* tb = tab + p0 + lane;
            #pragma unroll
            for (int it = 0; it < 22; it++) tw[it] = tb[it * 32];
        }

        const char* bu0 = (const char*)(Uc + r * 41);
        const char* bv0 = (const char*)(Vc + r * 41);
        const char* bu1 = (const char*)(Uc + (r + 32) * 41);
        const char* bv1 = (const char*)(Vc + (r + 32) * 41);
        float* po0 = outb + r * PN;
        float* po1 = outb + (r + 32) * PN;

        // head: p in [0, p0), both rows
        if (lane < p0) {
            unsigned t = tab[lane];
            float u0 = *(const float*)(bu0 + (t & 0xFFFFu));
            float v0 = *(const float*)(bv0 + (t >> 16));
            float u1 = *(const float*)(bu1 + (t & 0xFFFFu));
            float v1 = *(const float*)(bv1 + (t >> 16));
            __stcs(po0 + lane, fmaxf(u0 + v0, 0.f));
            __stcs(po1 + lane, fmaxf(u1 + v1, 0.f));
        }

        // main: 22 warp-iterations, both rows per iteration (2 indep chains)
        float* q0 = po0 + p0;
        float* q1 = po1 + p0;
        #pragma unroll
        for (int it = 0; it < 22; it++) {
            unsigned t = tw[it];
            unsigned ui = t & 0xFFFFu, vi = t >> 16;
            float u0 = *(const float*)(bu0 + ui);
            float v0 = *(const float*)(bv0 + vi);
            float u1 = *(const float*)(bu1 + ui);
            float v1 = *(const float*)(bv1 + vi);
            __stcs(q0 + it * 32 + lane, fmaxf(u0 + v0, 0.f));
            __stcs(q1 + it * 32 + lane, fmaxf(u1 + v1, 0.f));
        }

        // tail: p in [p0+704, 741), both rows
        int p = p0 + 704 + lane;
        #pragma unroll
        for (int tt = 0; tt < 2; tt++) {
            if (p < PN) {
                unsigned t = tab[p];
                float u0 = *(const float*)(bu0 + (t & 0xFFFFu));
                float v0 = *(const float*)(bv0 + (t >> 16));
                float u1 = *(const float*)(bu1 + (t & 0xFFFFu));
                float v1 = *(const float*)(bv1 + (t >> 16));
                __stcs(po0 + p, fmaxf(u0 + v0, 0.f));
                __stcs(po1 + p, fmaxf(u1 + v1, 0.f));
            }
            p += 32;
        }
    }
}

extern "C" void kernel_launch(void* const* d_in, const int* in_sizes, int n_in,
                              void* d_out, int out_size)
{
    const float* x    = (const float*)d_in[0];
    const float* W    = (const float*)d_in[1];
    const float* bias = (const float*)d_in[2];
    float* out = (float*)d_out;

    const int B = in_sizes[0] / (FN * EN);   // 2048

    cudaFuncSetAttribute(interconv_kernel,
                         cudaFuncAttributeMaxDynamicSharedMemorySize, SMEM_BYTES);
    interconv_kernel<<<B, THREADS, SMEM_BYTES>>>(x, W, bias, out);
}

// round 17
// speedup vs baseline: 1.0976x; 1.0976x over previous
#include <cuda_runtime.h>

// InterConv: B=2048, F=39, E=64, C=64, P=741
// out[b, c*P + p] = relu( U[c][ii[p]] + V[c][jj[p]] ),  U = x@Wi^T + bias, V = x@Wj^T
//
// Static-persistent kernel: grid = 4*numSMs; CTA bid processes b = bid + k*gridDim.
// W (XOR-swizzled, unpadded) and tab are staged ONCE per CTA; per batch only x
// is staged.  Per-batch body is identical to the 86.1us R11 kernel.
//
// smem (floats), 56.7 KB -> 4 CTAs/SM (226.9 KB):
//   persistent: Wi [0,4096)  Wj [4096,8192)   (f4 unit = c*16 + (e4 ^ (c&7)))
//               tab [8192,8936)
//   per batch:  xs [8936,11496)  (unpadded; phase-1 reads are warp-broadcast)
//               overlay after phase 1: Uc [8936,11560)   Vc [11560,14184)

#define FN 39
#define EN 64
#define CN 64
#define PN 741            // 39*38/2
#define OUTB (CN * PN)    // 47424 floats per batch
#define THREADS 256

#define WI_OFF  0
#define WJ_OFF  4096
#define TAB_OFF 8192
#define XS_OFF  8936                    // xs uses 2560; Uc overlay uses 2624
#define UC_OFF  8936
#define VC_OFF  11560
#define SMEM_FLOATS 14184
#define SMEM_BYTES  (SMEM_FLOATS * 4)   // 56736

// packed fp32x2 FMA (Blackwell; exact fp32 semantics, 2x FFMA throughput)
#define FMA_F32X2(acc, a, b) \
    asm("fma.rn.f32x2 %0, %1, %2, %0;" : "+l"(acc) : "l"(a), "l"(b))

extern __shared__ float smem[];

__global__ void __launch_bounds__(THREADS, 4)
interconv_kernel(const float* __restrict__ x,
                 const float* __restrict__ W,
                 const float* __restrict__ bias,
                 float* __restrict__ out,
                 int B)
{
    const int tid  = threadIdx.x;
    const int lane = tid & 31;
    const int wrp  = tid >> 5;
    unsigned* tab = (unsigned*)(smem + TAB_OFF);

    // ==== Once per CTA: stage W (XOR-swizzled) and build tab ==============
    {
        float4* Wi4 = (float4*)(smem + WI_OFF);
        float4* Wj4 = (float4*)(smem + WJ_OFF);
        const float4* Wg4 = (const float4*)W;
        #pragma unroll
        for (int it = 0; it < 8; it++) {
            int idx = tid + it * THREADS;           // 2048 float4 total
            int c = idx >> 5, q = idx & 31;
            int s = c & 7;
            float4 w = Wg4[idx];
            if (q < 16) Wi4[c * 16 + (q ^ s)] = w;
            else        Wj4[c * 16 + ((q - 16) ^ s)] = w;
        }
        // pair table (np.triu_indices(F,1) row-major): byte offsets i*4 | j*4<<16
        for (int p = tid; p < PN; p += THREADS) {
            int i = 0, rem = p;
            while (rem >= FN - 1 - i) { rem -= FN - 1 - i; i++; }
            int j = i + 1 + rem;
            tab[p] = (unsigned)(i * 4) | ((unsigned)(j * 4) << 16);
        }
    }

    const int c  = tid & 63;          // phase-1 ownership (fg const per warp)
    const int fg = tid >> 6;
    const int sxor = c & 7;
    const float bc = __ldg(bias + c);

    // ==== Batch loop =======================================================
    for (long long b = blockIdx.x; b < B; b += gridDim.x) {

        // loop-top sync: prior phase-2 reads of Uc/Vc done; covers W/tab on it 0
        __syncthreads();

        // ---- stage x (unpadded, coalesced float4) ------------------------
        {
            float4* xs4 = (float4*)(smem + XS_OFF);
            const float4* xb4 = (const float4*)(x + b * (long long)(FN * EN));
            #pragma unroll
            for (int it = 0; it < 3; it++) {
                int idx = tid + it * THREADS;
                if (idx < (FN * EN) / 4) xs4[idx] = xb4[idx];
            }
            if (tid < EN)                           // zero pad row f=39
                smem[XS_OFF + FN * EN + tid] = 0.f;
        }
        __syncthreads();

        // ---- Phase 1: U = x @ Wi^T + b, V = x @ Wj^T  (f32x2) ------------
        unsigned long long au[10], av[10];
        #pragma unroll
        for (int k = 0; k < 10; k++) { au[k] = 0ull; av[k] = 0ull; }

        {
            const ulonglong2* xs2 = (const ulonglong2*)(smem + XS_OFF);  // [f][16]
            const ulonglong2* Wi2 = (const ulonglong2*)(smem + WI_OFF);  // swizzled
            const ulonglong2* Wj2 = (const ulonglong2*)(smem + WJ_OFF);

            #pragma unroll
            for (int e4 = 0; e4 < 16; e4++) {
                ulonglong2 wi = Wi2[c * 16 + (e4 ^ sxor)];
                ulonglong2 wj = Wj2[c * 16 + (e4 ^ sxor)];
                #pragma unroll
                for (int k = 0; k < 10; k++) {
                    ulonglong2 xv = xs2[(fg + 4 * k) * 16 + e4];  // f=39 zeros
                    FMA_F32X2(au[k], xv.x, wi.x);
                    FMA_F32X2(au[k], xv.y, wi.y);
                    FMA_F32X2(av[k], xv.x, wj.x);
                    FMA_F32X2(av[k], xv.y, wj.y);
                }
            }
        }
        __syncthreads();   // all xs reads done; Uc may overlay xs

        // ---- Phase 1b: write Uc/Vc (transposed, stride 41) ---------------
        float* Uc = smem + UC_OFF;                 // [c][41]
        float* Vc = smem + VC_OFF;                 // [c][41]
        {
            #pragma unroll
            for (int k = 0; k < 10; k++) {
                int f = fg + 4 * k;                // f<=39; f=39 lands in pad
                float ulo = __uint_as_float((unsigned)au[k]);
                float uhi = __uint_as_float((unsigned)(au[k] >> 32));
                float vlo = __uint_as_float((unsigned)av[k]);
                float vhi = __uint_as_float((unsigned)(av[k] >> 32));
                Uc[c * 41 + f] = ulo + uhi + bc;   // bias folded into U
                Vc[c * 41 + f] = vlo + vhi;
            }
        }
        __syncthreads();

        // ---- Phase 2: expansion + relu, fused row pairs, register tab ----
        float* outb = out + b * (long long)OUTB;

        #pragma unroll 1
        for (int k = 0; k < 4; k++) {
            const int r  = wrp * 4 + k;           // rows r and r+32 share p0
            const int p0 = (27 * r) & 31;

            // preload the 22-entry aligned tab window into registers
            unsigned tw[22];
            {
                const unsigned* tb = tab + p0 + lane;
                #pragma unroll
                for (int it = 0; it < 22; it++) tw[it] = tb[it * 32];
            }

            const char* bu0 = (const char*)(Uc + r * 41);
            const char* bv0 = (const char*)(Vc + r * 41);
            const char* bu1 = (const char*)(Uc + (r + 32) * 41);
            const char* bv1 = (const char*)(Vc + (r + 32) * 41);
            float* po0 = outb + r * PN;
            float* po1 = outb + (r + 32) * PN;

            // head: p in [0, p0), both rows
            if (lane < p0) {
                unsigned t = tab[lane];
                float u0 = *(const float*)(bu0 + (t & 0xFFFFu));
                float v0 = *(const float*)(bv0 + (t >> 16));
                float u1 = *(const float*)(bu1 + (t & 0xFFFFu));
                float v1 = *(const float*)(bv1 + (t >> 16));
                __stcs(po0 + lane, fmaxf(u0 + v0, 0.f));
                __stcs(po1 + lane, fmaxf(u1 + v1, 0.f));
            }

            // main: 22 warp-iterations, both rows per iteration
            float* q0 = po0 + p0;
            float* q1 = po1 + p0;
            #pragma unroll
            for (int it = 0; it < 22; it++) {
                unsigned t = tw[it];
                unsigned ui = t & 0xFFFFu, vi = t >> 16;
                float u0 = *(const float*)(bu0 + ui);
                float v0 = *(const float*)(bv0 + vi);
                float u1 = *(const float*)(bu1 + ui);
                float v1 = *(const float*)(bv1 + vi);
                __stcs(q0 + it * 32 + lane, fmaxf(u0 + v0, 0.f));
                __stcs(q1 + it * 32 + lane, fmaxf(u1 + v1, 0.f));
            }

            // tail: p in [p0+704, 741), both rows
            int p = p0 + 704 + lane;
            #pragma unroll
            for (int tt = 0; tt < 2; tt++) {
                if (p < PN) {
                    unsigned t = tab[p];
                    float u0 = *(const float*)(bu0 + (t & 0xFFFFu));
                    float v0 = *(const float*)(bv0 + (t >> 16));
                    float u1 = *(const float*)(bu1 + (t & 0xFFFFu));
                    float v1 = *(const float*)(bv1 + (t >> 16));
                    __stcs(po0 + p, fmaxf(u0 + v0, 0.f));
                    __stcs(po1 + p, fmaxf(u1 + v1, 0.f));
                }
                p += 32;
            }
        }
    }
}

extern "C" void kernel_launch(void* const* d_in, const int* in_sizes, int n_in,
                              void* d_out, int out_size)
{
    const float* x    = (const float*)d_in[0];
    const float* W    = (const float*)d_in[1];
    const float* bias = (const float*)d_in[2];
    float* out = (float*)d_out;

    const int B = in_sizes[0] / (FN * EN);   // 2048

    int dev = 0, sms = 148;
    cudaGetDevice(&dev);
    cudaDeviceGetAttribute(&sms, cudaDevAttrMultiProcessorCount, dev);

    cudaFuncSetAttribute(interconv_kernel,
                         cudaFuncAttributeMaxDynamicSharedMemorySize, SMEM_BYTES);
    interconv_kernel<<<sms * 4, THREADS, SMEM_BYTES>>>(x, W, bias, out, B);
}